// round 2
// baseline (speedup 1.0000x reference)
#include <cuda_runtime.h>

#define S_ 512
#define L_ 256
#define H_ 768
#define P_ 8
#define K_ 8
#define H4_ (H_/4)          // 192
#define SPAN_ (P_*K_)       // 64 entries per role
#define THREADS_ 192

__global__ __launch_bounds__(THREADS_, 1)
void srl_pool_kernel(const float* __restrict__ emb,
                     const int* __restrict__ idxV,  const int* __restrict__ mV,
                     const int* __restrict__ idxA0, const int* __restrict__ mA0,
                     const int* __restrict__ idxA1, const int* __restrict__ mA1,
                     const int* __restrict__ pred,
                     float* __restrict__ out)
{
    const int s   = blockIdx.x;
    const int tid = threadIdx.x;

    __shared__ int   s_idx[3][SPAN_];
    __shared__ float s_w[3][SPAN_];
    __shared__ int   s_n[3];

    // Pre-zero the compacted lists (192 threads cover exactly 3*64 slots)
    {
        int r = tid >> 6, j = tid & 63;
        s_idx[r][j] = 0;
        s_w[r][j]   = 0.0f;
    }
    if (tid < 3) s_n[tid] = 0;
    __syncthreads();

    // Phase 1: 24 threads, one per (role, p). Fold all gating + divisions into
    // a single per-entry weight, compact non-zero entries.
    if (tid < 3 * P_) {
        const int role = tid >> 3;
        const int p    = tid & 7;
        const int* __restrict__ idx =
            (role == 0) ? idxV : (role == 1) ? idxA0 : idxA1;
        const int* __restrict__ msk =
            (role == 0) ? mV : (role == 1) ? mA0 : mA1;

        const int base = (s * P_ + p) * K_;
        int li[K_];
        int lv[K_];
        int cnt = 0;
        #pragma unroll
        for (int k = 0; k < K_; k++) {
            int ix = idx[base + k];
            int v  = (msk[base + k] != 0) & (ix < L_) & (ix >= 0);
            li[k]  = min(max(ix, 0), L_ - 1);
            lv[k]  = v;
            cnt   += v;
        }

        int npred = 0;
        #pragma unroll
        for (int q = 0; q < P_; q++) npred += (pred[s * P_ + q] != 0);

        float w = 0.0f;
        if ((pred[s * P_ + p] != 0) && cnt > 0 && npred > 0)
            w = 1.0f / ((float)cnt * (float)npred);

        if (w != 0.0f) {
            int pos = atomicAdd(&s_n[role], cnt);
            #pragma unroll
            for (int k = 0; k < K_; k++) {
                if (lv[k]) {
                    s_idx[role][pos] = li[k];
                    s_w[role][pos]   = w;
                    pos++;
                }
            }
        }
    }
    __syncthreads();

    // Phase 2: weighted row-sum. Each thread owns one float4 column slice.
    const float4* __restrict__ emb4 =
        reinterpret_cast<const float4*>(emb) + (size_t)s * L_ * H4_;

    float4 a0 = make_float4(0.f, 0.f, 0.f, 0.f);
    float4 a1 = a0, a2 = a0;

    // Round counts up to multiple of 4; padded slots have w=0, idx=0 (harmless load of row 0).
    const int n0 = (s_n[0] + 3) & ~3;
    const int n1 = (s_n[1] + 3) & ~3;
    const int n2 = (s_n[2] + 3) & ~3;

    #define AXPY_LOOP(ACC, R, NR)                                              \
    for (int j = 0; j < (NR); j += 4) {                                        \
        float w0 = s_w[R][j + 0], w1 = s_w[R][j + 1];                          \
        float w2 = s_w[R][j + 2], w3 = s_w[R][j + 3];                          \
        int   i0 = s_idx[R][j + 0], i1 = s_idx[R][j + 1];                      \
        int   i2 = s_idx[R][j + 2], i3 = s_idx[R][j + 3];                      \
        float4 v0 = emb4[i0 * H4_ + tid];                                      \
        float4 v1 = emb4[i1 * H4_ + tid];                                      \
        float4 v2 = emb4[i2 * H4_ + tid];                                      \
        float4 v3 = emb4[i3 * H4_ + tid];                                      \
        ACC.x += w0 * v0.x; ACC.y += w0 * v0.y; ACC.z += w0 * v0.z; ACC.w += w0 * v0.w; \
        ACC.x += w1 * v1.x; ACC.y += w1 * v1.y; ACC.z += w1 * v1.z; ACC.w += w1 * v1.w; \
        ACC.x += w2 * v2.x; ACC.y += w2 * v2.y; ACC.z += w2 * v2.z; ACC.w += w2 * v2.w; \
        ACC.x += w3 * v3.x; ACC.y += w3 * v3.y; ACC.z += w3 * v3.z; ACC.w += w3 * v3.w; \
    }

    AXPY_LOOP(a0, 0, n0)
    AXPY_LOOP(a1, 1, n1)
    AXPY_LOOP(a2, 2, n2)
    #undef AXPY_LOOP

    // Output: tuple (e_V, e_A0, e_A1) concatenated role-major, each (S, H) f32.
    float4* __restrict__ out4 = reinterpret_cast<float4*>(out);
    out4[((size_t)0 * S_ + s) * H4_ + tid] = a0;
    out4[((size_t)1 * S_ + s) * H4_ + tid] = a1;
    out4[((size_t)2 * S_ + s) * H4_ + tid] = a2;
}

extern "C" void kernel_launch(void* const* d_in, const int* in_sizes, int n_in,
                              void* d_out, int out_size)
{
    const float* emb   = (const float*)d_in[0];
    const int*   idxV  = (const int*)d_in[1];
    const int*   mV    = (const int*)d_in[2];
    const int*   idxA0 = (const int*)d_in[3];
    const int*   mA0   = (const int*)d_in[4];
    const int*   idxA1 = (const int*)d_in[5];
    const int*   mA1   = (const int*)d_in[6];
    const int*   pred  = (const int*)d_in[7];
    float* out = (float*)d_out;

    srl_pool_kernel<<<S_, THREADS_>>>(emb, idxV, mV, idxA0, mA0, idxA1, mA1, pred, out);
}